// round 11
// baseline (speedup 1.0000x reference)
#include <cuda_runtime.h>

// Problem constants (fixed by the dataset): B=2, C=6, H=W=512, radii {2,4}
#define HH 512
#define WW 512
#define HW (HH * WW)
#define CC 6
#define CCA_EPS 1e-6f

typedef unsigned long long u64;

// ---------- packed f32x2 helpers (sm_103a FFMA2 path) ----------
static __device__ __forceinline__ u64 pk2(float lo, float hi) {
    u64 r; asm("mov.b64 %0, {%1, %2};" : "=l"(r) : "f"(lo), "f"(hi)); return r;
}
static __device__ __forceinline__ u64 bc2(float v) {
    u64 r; asm("mov.b64 %0, {%1, %1};" : "=l"(r) : "f"(v)); return r;
}
static __device__ __forceinline__ void fma2(u64& d, u64 a, u64 b) {
    asm("fma.rn.f32x2 %0, %1, %2, %0;" : "+l"(d) : "l"(a), "l"(b));
}
static __device__ __forceinline__ u64 fma2v(u64 d, u64 a, u64 b) {
    asm("fma.rn.f32x2 %0, %1, %2, %0;" : "+l"(d) : "l"(a), "l"(b));
    return d;
}
static __device__ __forceinline__ u64 mul2v(u64 a, u64 b) {
    u64 r; asm("mul.rn.f32x2 %0, %1, %2;" : "=l"(r) : "l"(a), "l"(b));
    return r;
}
static __device__ __forceinline__ void add2(u64& d, u64 a) {
    asm("add.rn.f32x2 %0, %0, %1;" : "+l"(d) : "l"(a));
}
static __device__ __forceinline__ void sub2(u64& d, u64 a) {
    asm("sub.rn.f32x2 %0, %0, %1;" : "+l"(d) : "l"(a));
}
static __device__ __forceinline__ void up2(u64 v, float& a, float& b) {
    asm("mov.b64 {%0, %1}, %2;" : "=f"(a), "=f"(b) : "l"(v));
}

static __device__ __forceinline__ int refl(int p, int n) {
    // jnp.pad mode='reflect': -1 -> 1, n -> n-2
    return p < 0 ? -p : (p >= n ? 2 * n - 2 - p : p);
}

// Packed lower-triangular index (i >= j)
static __device__ __host__ __forceinline__ constexpr int P(int i, int j) {
    return i * (i + 1) / 2 + j;
}

// Window-sum state, f32x2-packed along j.
struct Acc {
    u64 xx[9];   // XX triangle pairs: (1:01)(2:01)(3:01)(3:23)(4:01)(4:23)(5:01)(5:23)(5:45)
    u64 yy[9];
    u64 xy[18];  // full 6x6, row i pairs p=0..2
    u64 mx[3], my[3];
    float dxx[3];  // XX diag leftovers: (0,0) (2,2) (4,4)
    float dyy[3];
};

static __device__ __forceinline__ void acc_zero(Acc& A) {
#pragma unroll
    for (int t = 0; t < 9; t++) { A.xx[t] = 0ULL; A.yy[t] = 0ULL; }
#pragma unroll
    for (int t = 0; t < 18; t++) A.xy[t] = 0ULL;
#pragma unroll
    for (int t = 0; t < 3; t++) {
        A.mx[t] = 0ULL; A.my[t] = 0ULL; A.dxx[t] = 0.f; A.dyy[t] = 0.f;
    }
}

// One sample's FMA work: SGN=+1 add, SGN=-1 retire.
template <int SGN>
static __device__ __forceinline__ void sample_fma(const float xv[CC], const float yv[CC], Acc& A) {
    float mxv[CC], myv[CC];
#pragma unroll
    for (int a = 0; a < CC; a++) {
        mxv[a] = (SGN > 0) ? xv[a] : -xv[a];
        myv[a] = (SGN > 0) ? yv[a] : -yv[a];
    }
    u64 xp[3], yp[3];
#pragma unroll
    for (int p = 0; p < 3; p++) {
        xp[p] = pk2(xv[2 * p], xv[2 * p + 1]);
        yp[p] = pk2(yv[2 * p], yv[2 * p + 1]);
    }
    u64 bx[6], by[6];
#pragma unroll
    for (int a = 0; a < 6; a++) bx[a] = bc2(mxv[a]);
#pragma unroll
    for (int a = 1; a < 6; a++) by[a] = bc2(myv[a]);

    // XX triangle
    fma2(A.xx[0], bx[1], xp[0]);
    fma2(A.xx[1], bx[2], xp[0]);
    fma2(A.xx[2], bx[3], xp[0]); fma2(A.xx[3], bx[3], xp[1]);
    fma2(A.xx[4], bx[4], xp[0]); fma2(A.xx[5], bx[4], xp[1]);
    fma2(A.xx[6], bx[5], xp[0]); fma2(A.xx[7], bx[5], xp[1]); fma2(A.xx[8], bx[5], xp[2]);
    A.dxx[0] = fmaf(mxv[0], xv[0], A.dxx[0]);
    A.dxx[1] = fmaf(mxv[2], xv[2], A.dxx[1]);
    A.dxx[2] = fmaf(mxv[4], xv[4], A.dxx[2]);
    // YY triangle
    fma2(A.yy[0], by[1], yp[0]);
    fma2(A.yy[1], by[2], yp[0]);
    fma2(A.yy[2], by[3], yp[0]); fma2(A.yy[3], by[3], yp[1]);
    fma2(A.yy[4], by[4], yp[0]); fma2(A.yy[5], by[4], yp[1]);
    fma2(A.yy[6], by[5], yp[0]); fma2(A.yy[7], by[5], yp[1]); fma2(A.yy[8], by[5], yp[2]);
    A.dyy[0] = fmaf(myv[0], yv[0], A.dyy[0]);
    A.dyy[1] = fmaf(myv[2], yv[2], A.dyy[1]);
    A.dyy[2] = fmaf(myv[4], yv[4], A.dyy[2]);
    // XY full
#pragma unroll
    for (int i = 0; i < 6; i++) {
        fma2(A.xy[i * 3 + 0], bx[i], yp[0]);
        fma2(A.xy[i * 3 + 1], bx[i], yp[1]);
        fma2(A.xy[i * 3 + 2], bx[i], yp[2]);
    }
    // means
    if (SGN > 0) {
#pragma unroll
        for (int p = 0; p < 3; p++) { add2(A.mx[p], xp[p]); add2(A.my[p], yp[p]); }
    } else {
#pragma unroll
        for (int p = 0; p < 3; p++) { sub2(A.mx[p], xp[p]); sub2(A.my[p], yp[p]); }
    }
}

// Priming: accumulate one padded row.
template <int R>
static __device__ __forceinline__ void accum_row(const float* __restrict__ xb,
                                                 const float* __restrict__ yb,
                                                 int row, int xcol, Acc& A) {
    const int rbase = refl(row, HH) * WW;
#pragma unroll 1
    for (int dx = -R; dx <= R; ++dx) {
        const int base = rbase + refl(xcol + dx, WW);
        float xv[CC], yv[CC];
#pragma unroll
        for (int a = 0; a < CC; a++) {
            xv[a] = __ldg(xb + a * HW + base);
            yv[a] = __ldg(yb + a * HW + base);
        }
        sample_fma<1>(xv, yv, A);
    }
}

// Fused slide: add row `rowAdd`, retire row `rowRet` (both padded row indices).
// Per dx iteration: 24 loads batched up front, then 2x independent FMA blocks.
template <int R>
static __device__ __forceinline__ void step_rows(const float* __restrict__ xb,
                                                 const float* __restrict__ yb,
                                                 int rowAdd, int rowRet, int xcol, Acc& A) {
    const int baseA = refl(rowAdd, HH) * WW;
    const int baseR = refl(rowRet, HH) * WW;
#pragma unroll (R == 2 ? 5 : 3)
    for (int dx = -R; dx <= R; ++dx) {
        const int c = refl(xcol + dx, WW);
        const int ia = baseA + c;
        const int ir = baseR + c;
        float xa[CC], ya[CC], xr[CC], yr[CC];
#pragma unroll
        for (int a = 0; a < CC; a++) {
            xa[a] = __ldg(xb + a * HW + ia);
            ya[a] = __ldg(yb + a * HW + ia);
            xr[a] = __ldg(xb + a * HW + ir);
            yr[a] = __ldg(yb + a * HW + ir);
        }
        sample_fma<1>(xa, ya, A);
        sample_fma<-1>(xr, yr, A);
    }
}

// In-place: packed-lower SPD matrix -> packed-lower inv(chol(c)).
static __device__ __forceinline__ void chol_inv6(float* c) {
    float L[21];  // off-diagonals hold L[i][j]; diagonal slots hold 1/L[j][j]
#pragma unroll
    for (int j = 0; j < 6; j++) {
        float d = c[P(j, j)];
#pragma unroll
        for (int k = 0; k < j; k++) d = fmaf(-L[P(j, k)], L[P(j, k)], d);
        const float rs = rsqrtf(d);
        L[P(j, j)] = rs;
#pragma unroll
        for (int i = j + 1; i < 6; i++) {
            float s = c[P(i, j)];
#pragma unroll
            for (int k = 0; k < j; k++) s = fmaf(-L[P(i, k)], L[P(j, k)], s);
            L[P(i, j)] = s * rs;
        }
    }
    // Forward substitution: M = L^{-1}, written back into c
#pragma unroll
    for (int j = 0; j < 6; j++) {
        c[P(j, j)] = L[P(j, j)];
#pragma unroll
        for (int i = j + 1; i < 6; i++) {
            float s = 0.f;
#pragma unroll
            for (int k = j; k < i; k++) s = fmaf(L[P(i, k)], c[P(k, j)], s);
            c[P(i, j)] = -L[P(i, i)] * s;
        }
    }
}

// Epilogue on RAW window sums. CCA correlation is invariant to scaling the
// covariance by n (Cholesky absorbs sqrt(n) on each side), so we use
//   chat = n*cov = S2 - (S1_i)*(S1_j/n),  with eps scaled to n*eps.
template <int R>
static __device__ __forceinline__ float cca_epilogue(const Acc& A) {
    constexpr float inv_n = 1.0f / float((2 * R + 1) * (2 * R + 1));
    constexpr float neps = CCA_EPS * float((2 * R + 1) * (2 * R + 1));

    float sxm[6], sym[6];
#pragma unroll
    for (int p = 0; p < 3; p++) {
        up2(A.mx[p], sxm[2 * p], sxm[2 * p + 1]);
        up2(A.my[p], sym[2 * p], sym[2 * p + 1]);
    }
    const u64 cni = bc2(-inv_n);
    u64 nsmx[3], nsmy[3];  // -(S1)/n, packed pairs
#pragma unroll
    for (int p = 0; p < 3; p++) {
        nsmx[p] = mul2v(A.mx[p], cni);
        nsmy[p] = mul2v(A.my[p], cni);
    }
    u64 bx[6], by[6];
#pragma unroll
    for (int a = 0; a < 6; a++) { bx[a] = bc2(sxm[a]); by[a] = bc2(sym[a]); }

    // chat pairs = S2_pair + bc2(S1_i) * nsm_pair
    float cxx[21], cyy[21], cxy[36];
    {
        u64 t;
        t = fma2v(A.xx[0], bx[1], nsmx[0]); up2(t, cxx[P(1, 0)], cxx[P(1, 1)]);
        t = fma2v(A.xx[1], bx[2], nsmx[0]); up2(t, cxx[P(2, 0)], cxx[P(2, 1)]);
        t = fma2v(A.xx[2], bx[3], nsmx[0]); up2(t, cxx[P(3, 0)], cxx[P(3, 1)]);
        t = fma2v(A.xx[3], bx[3], nsmx[1]); up2(t, cxx[P(3, 2)], cxx[P(3, 3)]);
        t = fma2v(A.xx[4], bx[4], nsmx[0]); up2(t, cxx[P(4, 0)], cxx[P(4, 1)]);
        t = fma2v(A.xx[5], bx[4], nsmx[1]); up2(t, cxx[P(4, 2)], cxx[P(4, 3)]);
        t = fma2v(A.xx[6], bx[5], nsmx[0]); up2(t, cxx[P(5, 0)], cxx[P(5, 1)]);
        t = fma2v(A.xx[7], bx[5], nsmx[1]); up2(t, cxx[P(5, 2)], cxx[P(5, 3)]);
        t = fma2v(A.xx[8], bx[5], nsmx[2]); up2(t, cxx[P(5, 4)], cxx[P(5, 5)]);
        t = fma2v(A.yy[0], by[1], nsmy[0]); up2(t, cyy[P(1, 0)], cyy[P(1, 1)]);
        t = fma2v(A.yy[1], by[2], nsmy[0]); up2(t, cyy[P(2, 0)], cyy[P(2, 1)]);
        t = fma2v(A.yy[2], by[3], nsmy[0]); up2(t, cyy[P(3, 0)], cyy[P(3, 1)]);
        t = fma2v(A.yy[3], by[3], nsmy[1]); up2(t, cyy[P(3, 2)], cyy[P(3, 3)]);
        t = fma2v(A.yy[4], by[4], nsmy[0]); up2(t, cyy[P(4, 0)], cyy[P(4, 1)]);
        t = fma2v(A.yy[5], by[4], nsmy[1]); up2(t, cyy[P(4, 2)], cyy[P(4, 3)]);
        t = fma2v(A.yy[6], by[5], nsmy[0]); up2(t, cyy[P(5, 0)], cyy[P(5, 1)]);
        t = fma2v(A.yy[7], by[5], nsmy[1]); up2(t, cyy[P(5, 2)], cyy[P(5, 3)]);
        t = fma2v(A.yy[8], by[5], nsmy[2]); up2(t, cyy[P(5, 4)], cyy[P(5, 5)]);
#pragma unroll
        for (int i = 0; i < 6; i++) {
#pragma unroll
            for (int p = 0; p < 3; p++) {
                t = fma2v(A.xy[i * 3 + p], bx[i], nsmy[p]);
                up2(t, cxy[i * 6 + 2 * p], cxy[i * 6 + 2 * p + 1]);
            }
        }
    }
    // diagonal leftovers + n*eps
    float nsx0, nsx1, nsx2, nsx3, nsx4, nsx5, nsy0, nsy1, nsy2, nsy3, nsy4, nsy5;
    up2(nsmx[0], nsx0, nsx1); up2(nsmx[1], nsx2, nsx3); up2(nsmx[2], nsx4, nsx5);
    up2(nsmy[0], nsy0, nsy1); up2(nsmy[1], nsy2, nsy3); up2(nsmy[2], nsy4, nsy5);
    cxx[P(0, 0)] = fmaf(sxm[0], nsx0, A.dxx[0]) + neps;
    cxx[P(2, 2)] = fmaf(sxm[2], nsx2, A.dxx[1]) + neps;
    cxx[P(4, 4)] = fmaf(sxm[4], nsx4, A.dxx[2]) + neps;
    cxx[P(1, 1)] += neps; cxx[P(3, 3)] += neps; cxx[P(5, 5)] += neps;
    cyy[P(0, 0)] = fmaf(sym[0], nsy0, A.dyy[0]) + neps;
    cyy[P(2, 2)] = fmaf(sym[2], nsy2, A.dyy[1]) + neps;
    cyy[P(4, 4)] = fmaf(sym[4], nsy4, A.dyy[2]) + neps;
    cyy[P(1, 1)] += neps; cyy[P(3, 3)] += neps; cyy[P(5, 5)] += neps;

    chol_inv6(cxx);  // Mx = inv(chol(n*Cxx)), packed lower
    chol_inv6(cyy);  // My = inv(chol(n*Cyy)), packed lower

    // corr_ii = sum_{j<=i} sum_{k>=i} Mx[i,j] * (n*Cxy)[j,k] * My[k,i]
    float sim = 0.f;
#pragma unroll
    for (int i = 0; i < 6; i++) {
        float corr = 0.f;
#pragma unroll
        for (int k = i; k < 6; k++) {
            float t = 0.f;
#pragma unroll
            for (int j = 0; j <= i; j++) t = fmaf(cxx[P(i, j)], cxy[j * 6 + k], t);
            corr = fmaf(t, cyy[P(k, i)], corr);
        }
        sim += fabsf(corr);
    }
    return sim * (1.0f / 6.0f);
}

// Tiling: 32 columns per warp, 4 warps per block, each thread slides a
// vertical window over RPW output rows of its column.
#define TW 32
#define WARPS 4
#define RPW 32
#define TILE_H (WARPS * RPW)

template <int R>
static __device__ void run_tile(const float* __restrict__ xb,
                                const float* __restrict__ yb,
                                float* __restrict__ ob,
                                int xcol, int y0, int ridx) {
    Acc A;
    acc_zero(A);
    // Prime the window with rows [y0-R-1, y0+R-1] (2R+1 rows; row y0-R-1 is
    // the stale row retired by the first fused step).
#pragma unroll 1
    for (int row = y0 - R - 1; row <= y0 + R - 1; ++row) accum_row<R>(xb, yb, row, xcol, A);
#pragma unroll 2
    for (int yy = y0; yy < y0 + RPW; ++yy) {
        step_rows<R>(xb, yb, yy + R, yy - R - 1, xcol, A);  // window -> [yy-R, yy+R]
        const float sim = cca_epilogue<R>(A);
        ob[((yy * WW + xcol) << 1) + ridx] = sim;
    }
}

__global__ void __launch_bounds__(TW * WARPS, 2)
PatchCCAConv_kernel(const float* __restrict__ x, const float* __restrict__ y,
                    float* __restrict__ out) {
    // z = 0,1 -> r=4 (long blocks scheduled first); z = 2,3 -> r=2
    const int b = blockIdx.z & 1;
    const bool is_r4 = blockIdx.z < 2;
    const int xcol = blockIdx.x * TW + threadIdx.x;
    const int y0 = blockIdx.y * TILE_H + threadIdx.y * RPW;
    const float* xb = x + b * CC * HW;
    const float* yb = y + b * CC * HW;
    float* ob = out + b * (HH * WW * 2);
    if (is_r4)
        run_tile<4>(xb, yb, ob, xcol, y0, 1);
    else
        run_tile<2>(xb, yb, ob, xcol, y0, 0);
}

extern "C" void kernel_launch(void* const* d_in, const int* in_sizes, int n_in,
                              void* d_out, int out_size) {
    const float* x = (const float*)d_in[0];
    const float* y = (const float*)d_in[1];
    float* out = (float*)d_out;
    (void)in_sizes; (void)n_in; (void)out_size;

    dim3 block(TW, WARPS, 1);
    dim3 grid(WW / TW, HH / TILE_H, 4);  // (16, 4, 4): z<2 r=4, z>=2 r=2
    PatchCCAConv_kernel<<<grid, block>>>(x, y, out);
}

// round 14
// speedup vs baseline: 1.6945x; 1.6945x over previous
#include <cuda_runtime.h>

// Problem constants (fixed by the dataset): B=2, C=6, H=W=512, radii {2,4}
#define HH 512
#define WW 512
#define HW (HH * WW)
#define CC 6
#define CCA_EPS 1e-6f

typedef unsigned long long u64;

// ---------- packed f32x2 helpers (sm_103a FFMA2 path) ----------
static __device__ __forceinline__ u64 pk2(float lo, float hi) {
    u64 r; asm("mov.b64 %0, {%1, %2};" : "=l"(r) : "f"(lo), "f"(hi)); return r;
}
static __device__ __forceinline__ u64 bc2(float v) {
    u64 r; asm("mov.b64 %0, {%1, %1};" : "=l"(r) : "f"(v)); return r;
}
static __device__ __forceinline__ void fma2(u64& d, u64 a, u64 b) {
    asm("fma.rn.f32x2 %0, %1, %2, %0;" : "+l"(d) : "l"(a), "l"(b));
}
static __device__ __forceinline__ u64 fma2v(u64 d, u64 a, u64 b) {
    asm("fma.rn.f32x2 %0, %1, %2, %0;" : "+l"(d) : "l"(a), "l"(b));
    return d;
}
static __device__ __forceinline__ u64 mul2v(u64 a, u64 b) {
    u64 r; asm("mul.rn.f32x2 %0, %1, %2;" : "=l"(r) : "l"(a), "l"(b));
    return r;
}
static __device__ __forceinline__ void add2(u64& d, u64 a) {
    asm("add.rn.f32x2 %0, %0, %1;" : "+l"(d) : "l"(a));
}
static __device__ __forceinline__ void sub2(u64& d, u64 a) {
    asm("sub.rn.f32x2 %0, %0, %1;" : "+l"(d) : "l"(a));
}
static __device__ __forceinline__ void up2(u64 v, float& a, float& b) {
    asm("mov.b64 {%0, %1}, %2;" : "=f"(a), "=f"(b) : "l"(v));
}

static __device__ __forceinline__ int refl(int p, int n) {
    // jnp.pad mode='reflect': -1 -> 1, n -> n-2
    return p < 0 ? -p : (p >= n ? 2 * n - 2 - p : p);
}

// Packed lower-triangular index (i >= j)
static __device__ __host__ __forceinline__ constexpr int P(int i, int j) {
    return i * (i + 1) / 2 + j;
}

// Window-sum state, f32x2-packed along j.
struct Acc {
    u64 xx[9];   // XX triangle pairs: (1:01)(2:01)(3:01)(3:23)(4:01)(4:23)(5:01)(5:23)(5:45)
    u64 yy[9];
    u64 xy[18];  // full 6x6, row i pairs p=0..2
    u64 mx[3], my[3];
    float dxx[3];  // XX diag leftovers: (0,0) (2,2) (4,4)
    float dyy[3];
};

static __device__ __forceinline__ void acc_zero(Acc& A) {
#pragma unroll
    for (int t = 0; t < 9; t++) { A.xx[t] = 0ULL; A.yy[t] = 0ULL; }
#pragma unroll
    for (int t = 0; t < 18; t++) A.xy[t] = 0ULL;
#pragma unroll
    for (int t = 0; t < 3; t++) {
        A.mx[t] = 0ULL; A.my[t] = 0ULL; A.dxx[t] = 0.f; A.dyy[t] = 0.f;
    }
}

// One sample's FMA work: SGN=+1 add, SGN=-1 retire.
template <int SGN>
static __device__ __forceinline__ void sample_fma(const float xv[CC], const float yv[CC], Acc& A) {
    float mxv[CC], myv[CC];
#pragma unroll
    for (int a = 0; a < CC; a++) {
        mxv[a] = (SGN > 0) ? xv[a] : -xv[a];
        myv[a] = (SGN > 0) ? yv[a] : -yv[a];
    }
    u64 xp[3], yp[3];
#pragma unroll
    for (int p = 0; p < 3; p++) {
        xp[p] = pk2(xv[2 * p], xv[2 * p + 1]);
        yp[p] = pk2(yv[2 * p], yv[2 * p + 1]);
    }
    u64 bx[6], by[6];
#pragma unroll
    for (int a = 0; a < 6; a++) bx[a] = bc2(mxv[a]);
#pragma unroll
    for (int a = 1; a < 6; a++) by[a] = bc2(myv[a]);

    // XX triangle
    fma2(A.xx[0], bx[1], xp[0]);
    fma2(A.xx[1], bx[2], xp[0]);
    fma2(A.xx[2], bx[3], xp[0]); fma2(A.xx[3], bx[3], xp[1]);
    fma2(A.xx[4], bx[4], xp[0]); fma2(A.xx[5], bx[4], xp[1]);
    fma2(A.xx[6], bx[5], xp[0]); fma2(A.xx[7], bx[5], xp[1]); fma2(A.xx[8], bx[5], xp[2]);
    A.dxx[0] = fmaf(mxv[0], xv[0], A.dxx[0]);
    A.dxx[1] = fmaf(mxv[2], xv[2], A.dxx[1]);
    A.dxx[2] = fmaf(mxv[4], xv[4], A.dxx[2]);
    // YY triangle
    fma2(A.yy[0], by[1], yp[0]);
    fma2(A.yy[1], by[2], yp[0]);
    fma2(A.yy[2], by[3], yp[0]); fma2(A.yy[3], by[3], yp[1]);
    fma2(A.yy[4], by[4], yp[0]); fma2(A.yy[5], by[4], yp[1]);
    fma2(A.yy[6], by[5], yp[0]); fma2(A.yy[7], by[5], yp[1]); fma2(A.yy[8], by[5], yp[2]);
    A.dyy[0] = fmaf(myv[0], yv[0], A.dyy[0]);
    A.dyy[1] = fmaf(myv[2], yv[2], A.dyy[1]);
    A.dyy[2] = fmaf(myv[4], yv[4], A.dyy[2]);
    // XY full
#pragma unroll
    for (int i = 0; i < 6; i++) {
        fma2(A.xy[i * 3 + 0], bx[i], yp[0]);
        fma2(A.xy[i * 3 + 1], bx[i], yp[1]);
        fma2(A.xy[i * 3 + 2], bx[i], yp[2]);
    }
    // means
    if (SGN > 0) {
#pragma unroll
        for (int p = 0; p < 3; p++) { add2(A.mx[p], xp[p]); add2(A.my[p], yp[p]); }
    } else {
#pragma unroll
        for (int p = 0; p < 3; p++) { sub2(A.mx[p], xp[p]); sub2(A.my[p], yp[p]); }
    }
}

// Priming: accumulate one padded row.
template <int R, bool XEDGE>
static __device__ __forceinline__ void accum_row(const float* __restrict__ xb,
                                                 const float* __restrict__ yb,
                                                 int row, int xcol, Acc& A) {
    const int rbase = refl(row, HH) * WW;
#pragma unroll 1
    for (int dx = -R; dx <= R; ++dx) {
        const int c = XEDGE ? refl(xcol + dx, WW) : (xcol + dx);
        const int base = rbase + c;
        float xv[CC], yv[CC];
#pragma unroll
        for (int a = 0; a < CC; a++) {
            xv[a] = __ldg(xb + a * HW + base);
            yv[a] = __ldg(yb + a * HW + base);
        }
        sample_fma<1>(xv, yv, A);
    }
}

// Fused slide: add row `rowAdd`, retire row `rowRet` (both padded row indices).
// Per dx iteration: 24 loads batched up front, then 2x independent FMA blocks.
template <int R, bool XEDGE>
static __device__ __forceinline__ void step_rows(const float* __restrict__ xb,
                                                 const float* __restrict__ yb,
                                                 int rowAdd, int rowRet, int xcol, Acc& A) {
    const int baseA = refl(rowAdd, HH) * WW;
    const int baseR = refl(rowRet, HH) * WW;
#pragma unroll (R == 2 ? 5 : 3)
    for (int dx = -R; dx <= R; ++dx) {
        const int c = XEDGE ? refl(xcol + dx, WW) : (xcol + dx);
        const int ia = baseA + c;
        const int ir = baseR + c;
        float xa[CC], ya[CC], xr[CC], yr[CC];
#pragma unroll
        for (int a = 0; a < CC; a++) {
            xa[a] = __ldg(xb + a * HW + ia);
            ya[a] = __ldg(yb + a * HW + ia);
            xr[a] = __ldg(xb + a * HW + ir);
            yr[a] = __ldg(yb + a * HW + ir);
        }
        sample_fma<1>(xa, ya, A);
        sample_fma<-1>(xr, yr, A);
    }
}

// In-place: packed-lower SPD matrix -> packed-lower inv(chol(c)).
static __device__ __forceinline__ void chol_inv6(float* c) {
    float L[21];  // off-diagonals hold L[i][j]; diagonal slots hold 1/L[j][j]
#pragma unroll
    for (int j = 0; j < 6; j++) {
        float d = c[P(j, j)];
#pragma unroll
        for (int k = 0; k < j; k++) d = fmaf(-L[P(j, k)], L[P(j, k)], d);
        const float rs = rsqrtf(d);
        L[P(j, j)] = rs;
#pragma unroll
        for (int i = j + 1; i < 6; i++) {
            float s = c[P(i, j)];
#pragma unroll
            for (int k = 0; k < j; k++) s = fmaf(-L[P(i, k)], L[P(j, k)], s);
            L[P(i, j)] = s * rs;
        }
    }
    // Forward substitution: M = L^{-1}, written back into c
#pragma unroll
    for (int j = 0; j < 6; j++) {
        c[P(j, j)] = L[P(j, j)];
#pragma unroll
        for (int i = j + 1; i < 6; i++) {
            float s = 0.f;
#pragma unroll
            for (int k = j; k < i; k++) s = fmaf(L[P(i, k)], c[P(k, j)], s);
            c[P(i, j)] = -L[P(i, i)] * s;
        }
    }
}

// Epilogue on RAW window sums. CCA correlation is invariant to scaling the
// covariance by n (Cholesky absorbs sqrt(n) on each side), so we use
//   chat = n*cov = S2 - (S1_i)*(S1_j/n),  with eps scaled to n*eps.
template <int R>
static __device__ __forceinline__ float cca_epilogue(const Acc& A) {
    constexpr float inv_n = 1.0f / float((2 * R + 1) * (2 * R + 1));
    constexpr float neps = CCA_EPS * float((2 * R + 1) * (2 * R + 1));

    float sxm[6], sym[6];
#pragma unroll
    for (int p = 0; p < 3; p++) {
        up2(A.mx[p], sxm[2 * p], sxm[2 * p + 1]);
        up2(A.my[p], sym[2 * p], sym[2 * p + 1]);
    }
    const u64 cni = bc2(-inv_n);
    u64 nsmx[3], nsmy[3];  // -(S1)/n, packed pairs
#pragma unroll
    for (int p = 0; p < 3; p++) {
        nsmx[p] = mul2v(A.mx[p], cni);
        nsmy[p] = mul2v(A.my[p], cni);
    }
    u64 bx[6], by[6];
#pragma unroll
    for (int a = 0; a < 6; a++) { bx[a] = bc2(sxm[a]); by[a] = bc2(sym[a]); }

    // chat pairs = S2_pair + bc2(S1_i) * nsm_pair
    float cxx[21], cyy[21], cxy[36];
    {
        u64 t;
        t = fma2v(A.xx[0], bx[1], nsmx[0]); up2(t, cxx[P(1, 0)], cxx[P(1, 1)]);
        t = fma2v(A.xx[1], bx[2], nsmx[0]); up2(t, cxx[P(2, 0)], cxx[P(2, 1)]);
        t = fma2v(A.xx[2], bx[3], nsmx[0]); up2(t, cxx[P(3, 0)], cxx[P(3, 1)]);
        t = fma2v(A.xx[3], bx[3], nsmx[1]); up2(t, cxx[P(3, 2)], cxx[P(3, 3)]);
        t = fma2v(A.xx[4], bx[4], nsmx[0]); up2(t, cxx[P(4, 0)], cxx[P(4, 1)]);
        t = fma2v(A.xx[5], bx[4], nsmx[1]); up2(t, cxx[P(4, 2)], cxx[P(4, 3)]);
        t = fma2v(A.xx[6], bx[5], nsmx[0]); up2(t, cxx[P(5, 0)], cxx[P(5, 1)]);
        t = fma2v(A.xx[7], bx[5], nsmx[1]); up2(t, cxx[P(5, 2)], cxx[P(5, 3)]);
        t = fma2v(A.xx[8], bx[5], nsmx[2]); up2(t, cxx[P(5, 4)], cxx[P(5, 5)]);
        t = fma2v(A.yy[0], by[1], nsmy[0]); up2(t, cyy[P(1, 0)], cyy[P(1, 1)]);
        t = fma2v(A.yy[1], by[2], nsmy[0]); up2(t, cyy[P(2, 0)], cyy[P(2, 1)]);
        t = fma2v(A.yy[2], by[3], nsmy[0]); up2(t, cyy[P(3, 0)], cyy[P(3, 1)]);
        t = fma2v(A.yy[3], by[3], nsmy[1]); up2(t, cyy[P(3, 2)], cyy[P(3, 3)]);
        t = fma2v(A.yy[4], by[4], nsmy[0]); up2(t, cyy[P(4, 0)], cyy[P(4, 1)]);
        t = fma2v(A.yy[5], by[4], nsmy[1]); up2(t, cyy[P(4, 2)], cyy[P(4, 3)]);
        t = fma2v(A.yy[6], by[5], nsmy[0]); up2(t, cyy[P(5, 0)], cyy[P(5, 1)]);
        t = fma2v(A.yy[7], by[5], nsmy[1]); up2(t, cyy[P(5, 2)], cyy[P(5, 3)]);
        t = fma2v(A.yy[8], by[5], nsmy[2]); up2(t, cyy[P(5, 4)], cyy[P(5, 5)]);
#pragma unroll
        for (int i = 0; i < 6; i++) {
#pragma unroll
            for (int p = 0; p < 3; p++) {
                t = fma2v(A.xy[i * 3 + p], bx[i], nsmy[p]);
                up2(t, cxy[i * 6 + 2 * p], cxy[i * 6 + 2 * p + 1]);
            }
        }
    }
    // diagonal leftovers + n*eps
    float nsx0, nsx1, nsx2, nsx3, nsx4, nsx5, nsy0, nsy1, nsy2, nsy3, nsy4, nsy5;
    up2(nsmx[0], nsx0, nsx1); up2(nsmx[1], nsx2, nsx3); up2(nsmx[2], nsx4, nsx5);
    up2(nsmy[0], nsy0, nsy1); up2(nsmy[1], nsy2, nsy3); up2(nsmy[2], nsy4, nsy5);
    cxx[P(0, 0)] = fmaf(sxm[0], nsx0, A.dxx[0]) + neps;
    cxx[P(2, 2)] = fmaf(sxm[2], nsx2, A.dxx[1]) + neps;
    cxx[P(4, 4)] = fmaf(sxm[4], nsx4, A.dxx[2]) + neps;
    cxx[P(1, 1)] += neps; cxx[P(3, 3)] += neps; cxx[P(5, 5)] += neps;
    cyy[P(0, 0)] = fmaf(sym[0], nsy0, A.dyy[0]) + neps;
    cyy[P(2, 2)] = fmaf(sym[2], nsy2, A.dyy[1]) + neps;
    cyy[P(4, 4)] = fmaf(sym[4], nsy4, A.dyy[2]) + neps;
    cyy[P(1, 1)] += neps; cyy[P(3, 3)] += neps; cyy[P(5, 5)] += neps;

    chol_inv6(cxx);  // Mx = inv(chol(n*Cxx)), packed lower
    chol_inv6(cyy);  // My = inv(chol(n*Cyy)), packed lower

    // corr_ii = sum_{j<=i} sum_{k>=i} Mx[i,j] * (n*Cxy)[j,k] * My[k,i]
    float sim = 0.f;
#pragma unroll
    for (int i = 0; i < 6; i++) {
        float corr = 0.f;
#pragma unroll
        for (int k = i; k < 6; k++) {
            float t = 0.f;
#pragma unroll
            for (int j = 0; j <= i; j++) t = fmaf(cxx[P(i, j)], cxy[j * 6 + k], t);
            corr = fmaf(t, cyy[P(k, i)], corr);
        }
        sim += fabsf(corr);
    }
    return sim * (1.0f / 6.0f);
}

// Tiling: 32 columns per warp, 4 warps per block, each thread slides a
// vertical window over RPW output rows of its column.
#define TW 32
#define WARPS 4
#define RPW 16
#define TILE_H (WARPS * RPW)

template <int R, bool XEDGE>
static __device__ void run_tile(const float* __restrict__ xb,
                                const float* __restrict__ yb,
                                float* __restrict__ ob,
                                int xcol, int y0, int ridx) {
    Acc A;
    acc_zero(A);
    // Prime the window with rows [y0-R-1, y0+R-1] (2R+1 rows; row y0-R-1 is
    // the stale row retired by the first fused step).
#pragma unroll 1
    for (int row = y0 - R - 1; row <= y0 + R - 1; ++row) accum_row<R, XEDGE>(xb, yb, row, xcol, A);
#pragma unroll 1
    for (int yy = y0; yy < y0 + RPW; ++yy) {
        step_rows<R, XEDGE>(xb, yb, yy + R, yy - R - 1, xcol, A);  // window -> [yy-R, yy+R]
        const float sim = cca_epilogue<R>(A);
        ob[((yy * WW + xcol) << 1) + ridx] = sim;
    }
}

__global__ void __launch_bounds__(TW * WARPS, 3)
PatchCCAConv_kernel(const float* __restrict__ x, const float* __restrict__ y,
                    float* __restrict__ out) {
    // z = 0,1 -> r=4 (long blocks scheduled first); z = 2,3 -> r=2
    const int b = blockIdx.z & 1;
    const bool is_r4 = blockIdx.z < 2;
    const int xcol = blockIdx.x * TW + threadIdx.x;
    const int y0 = blockIdx.y * TILE_H + threadIdx.y * RPW;
    const bool xedge = (blockIdx.x == 0) || (blockIdx.x == (WW / TW - 1));
    const float* xb = x + b * CC * HW;
    const float* yb = y + b * CC * HW;
    float* ob = out + b * (HH * WW * 2);
    if (is_r4) {
        if (xedge) run_tile<4, true>(xb, yb, ob, xcol, y0, 1);
        else       run_tile<4, false>(xb, yb, ob, xcol, y0, 1);
    } else {
        if (xedge) run_tile<2, true>(xb, yb, ob, xcol, y0, 0);
        else       run_tile<2, false>(xb, yb, ob, xcol, y0, 0);
    }
}

extern "C" void kernel_launch(void* const* d_in, const int* in_sizes, int n_in,
                              void* d_out, int out_size) {
    const float* x = (const float*)d_in[0];
    const float* y = (const float*)d_in[1];
    float* out = (float*)d_out;
    (void)in_sizes; (void)n_in; (void)out_size;

    dim3 block(TW, WARPS, 1);
    dim3 grid(WW / TW, HH / TILE_H, 4);  // (16, 8, 4): z<2 r=4, z>=2 r=2
    PatchCCAConv_kernel<<<grid, block>>>(x, y, out);
}